// round 17
// baseline (speedup 1.0000x reference)
#include <cuda_runtime.h>
#include <cuda_bf16.h>
#include <cstdint>

#define NN 128
#define CC 64
#define TT 256
#define VV 25
#define DD 64
#define RR 16
#define FEAT 1600
#define ROWS (NN*TT)
#define TTILE 8                 // frames per gemm tile (warp = frame)
#define NTILES 4                // tiles per block (32 frames)
#define BUFW 1664               // epilogue strip stride (floats)

typedef unsigned long long u64;

// ---- gemm smem layout (bytes) ----
#define O_AT0 0                 // buf0: 8 fr x 2 half x 4096 = 65536
#define O_AT1 65536             // buf1: 65536
#define O_WTH 131072            // 64 x 128 = 8192
#define O_WTL 139264            // 8192
#define O_BUF 147456            // 8 x 1664 x 4 = 53248
#define O_IV  200704            // 2048 shorts = 4096
#define O_BFS 204800            // 64 floats = 256
#define SM_BYTES 205056

// ---- preshift smem layout ----
#define PS_RAW 0                // 64 x 200 floats = 51200
#define PS_IMG 51200            // 16 x 825 u32 = 52800
#define PS_SMEM 104000

// ---------------- device scratch ---------------------------------------------
__device__ float g_pooled[NN*CC];
__device__ float g_gate[NN*4];
__device__ float g_bf[NN*DD];
__device__ uint32_t g_Ah[(size_t)ROWS*800];     // 105MB bf16-pair A hi images
__device__ uint32_t g_Al[(size_t)ROWS*800];     // 105MB lo
__device__ uint32_t g_Wspu[NN*2*2048];          // W^T hi/lo swizzled images
__device__ float g_z[(size_t)NN*CC*TT*VV];      // pre-BN z, [n][d][t][v]
__device__ float g_sum[FEAT];
__device__ float g_sumsq[FEAT];
__device__ float4 g_tpv[800];                   // [v][c2]: {tm0, src0, tm1, src1}
__device__ short g_iv2[2048];                   // [d][v32]: y(v,d) -> strip slot

// ---------------- helpers ----------------------------------------------------
__device__ __forceinline__ uint32_t smem_u32(const void* p) {
    uint32_t a;
    asm("{ .reg .u64 t; cvta.to.shared.u64 t, %1; cvt.u32.u64 %0, t; }" : "=r"(a) : "l"(p));
    return a;
}
__device__ __forceinline__ void ldm4(uint32_t addr, uint32_t* r) {
    asm volatile("ldmatrix.sync.aligned.m8n8.x4.shared.b16 {%0,%1,%2,%3}, [%4];"
        : "=r"(r[0]), "=r"(r[1]), "=r"(r[2]), "=r"(r[3]) : "r"(addr));
}
__device__ __forceinline__ void mma16816(float* c, const uint32_t* a, const uint32_t* b) {
    asm volatile("mma.sync.aligned.m16n8k16.row.col.f32.bf16.bf16.f32 "
        "{%0,%1,%2,%3}, {%4,%5,%6,%7}, {%8,%9}, {%0,%1,%2,%3};"
        : "+f"(c[0]), "+f"(c[1]), "+f"(c[2]), "+f"(c[3])
        : "r"(a[0]), "r"(a[1]), "r"(a[2]), "r"(a[3]), "r"(b[0]), "r"(b[1]));
}
__device__ __forceinline__ void cp_async16(uint32_t dst, const void* src) {
    asm volatile("cp.async.cg.shared.global [%0], [%1], 16;" :: "r"(dst), "l"(src));
}
#define CP_COMMIT() asm volatile("cp.async.commit_group;")
#define CP_WAIT0()  asm volatile("cp.async.wait_group 0;")
#define CP_WAIT1()  asm volatile("cp.async.wait_group 1;")
__device__ __forceinline__ uint32_t packbf(__nv_bfloat16 a, __nv_bfloat16 b) {
    return (uint32_t)__bfloat16_as_ushort(a) | ((uint32_t)__bfloat16_as_ushort(b) << 16);
}

// ---------------- kernel 0: tables + zeroing ---------------------------------
__global__ void table_kernel(const float* __restrict__ mask,
                             const int* __restrict__ shift_in,
                             const int* __restrict__ shift_out) {
    int tid = blockIdx.x*256 + threadIdx.x;     // grid 32 -> 8192
    if (tid < 800) {
        int v = tid >> 5, c2 = tid & 31;
        int c0 = 2*c2, c1 = c0 + 1;
        int s0 = shift_in[v*CC + c0];
        int s1 = shift_in[v*CC + c1];
        float4 rec;
        rec.x = tanhf(mask[v*CC + c0]) + 1.0f;
        rec.y = __int_as_float((s0 & 63)*200 + (s0 >> 6));
        rec.z = tanhf(mask[v*CC + c1]) + 1.0f;
        rec.w = __int_as_float((s1 & 63)*200 + (s1 >> 6));
        g_tpv[tid] = rec;
    }
    if (tid < FEAT) {
        g_sum[tid] = 0.f; g_sumsq[tid] = 0.f;
        int s = shift_out[tid];
        g_iv2[(s & 63)*32 + (s >> 6)] = (short)(tid + (tid >> 6));
    }
    if (tid < NN*CC) g_pooled[tid] = 0.f;
}

// ---------------- kernel 1: preshift (gather+mask+bf16 split) + pool ---------
// grid NN*32: block = (n, 8 frames). Writes swizzled ldmatrix images to global.
__global__ void __launch_bounds__(256, 2) preshift_kernel(const float* __restrict__ x0) {
    extern __shared__ __align__(16) char sm[];
    float* raw = (float*)(sm + PS_RAW);         // [c][200]
    uint32_t* img = (uint32_t*)(sm + PS_IMG);   // [t*2+h][825] (33-u32 rows)
    uint32_t sb = smem_u32(sm);

    int bid = blockIdx.x;
    int n = bid >> 5, tc = bid & 31;
    int tid = threadIdx.x;
    int w = tid >> 5, l = tid & 31;

    const float* xb = x0 + (size_t)n * CC * (TT*VV) + tc * (TTILE*VV);
    #pragma unroll
    for (int k = 0; k < 13; k++) {
        int i = tid + k*256;
        if (i < 3200) {
            int c = i / 50, q = i - c*50;
            cp_async16(sb + PS_RAW + (c*200 + q*4)*4, xb + (size_t)c*(TT*VV) + q*4);
        }
    }
    CP_COMMIT(); CP_WAIT0();
    __syncthreads();

    // pool partials (warp covers 8 channels)
    #pragma unroll
    for (int cc = 0; cc < 8; cc++) {
        int c = w*8 + cc;
        float s = 0.f;
        for (int i = l; i < 200; i += 32) s += raw[c*200 + i];
        #pragma unroll
        for (int off = 16; off; off >>= 1) s += __shfl_down_sync(0xffffffffu, s, off);
        if (l == 0) atomicAdd(&g_pooled[n*CC + c], s);
    }

    // gather + mask + bf16 split into 33-stride staging image (conflict-free)
    for (int i = tid; i < 6400; i += 256) {
        int t = i / 800, r = i - t*800;
        int c2 = r / 25, v = r - c2*25;
        float4 tp = g_tpv[v*32 + c2];
        int off = t*25;
        float v0 = raw[__float_as_int(tp.y) + off] * tp.x;
        float v1 = raw[__float_as_int(tp.w) + off] * tp.z;
        __nv_bfloat16 h0 = __float2bfloat16(v0);
        __nv_bfloat16 h1 = __float2bfloat16(v1);
        __nv_bfloat16 L0 = __float2bfloat16(v0 - __bfloat162float(h0));
        __nv_bfloat16 L1 = __float2bfloat16(v1 - __bfloat162float(h1));
        int slot = (((c2 >> 2) ^ (v & 7)) << 2) + (c2 & 3);
        img[(t*2)*825 + v*33 + slot]     = packbf(h0, h1);
        img[(t*2+1)*825 + v*33 + slot]   = packbf(L0, L1);
    }
    __syncthreads();

    // copy staging images to global (coalesced)
    size_t base = ((size_t)n*TT + tc*TTILE) * 800;
    for (int g = tid; g < 6400; g += 256) {
        int t = g / 800, r = g - t*800;
        int v = r >> 5, x = r & 31;
        g_Ah[base + g] = img[(t*2)*825 + v*33 + x];
        g_Al[base + g] = img[(t*2+1)*825 + v*33 + x];
    }
}

// ---------------- kernel 2: SE gate ------------------------------------------
__global__ void gate_kernel(const float* __restrict__ fc1_w, const float* __restrict__ fc1_b,
                            const float* __restrict__ fc2_w, const float* __restrict__ fc2_b,
                            const int* __restrict__ epoch_p) {
    int n = threadIdx.x;
    if (n >= NN) return;
    const float invP = 1.0f / (float)(TT*VV);
    float pooled[CC];
    #pragma unroll
    for (int c = 0; c < CC; c++) pooled[c] = g_pooled[n*CC + c] * invP;
    float h[RR];
    #pragma unroll
    for (int j = 0; j < RR; j++) {
        float s = fc1_b[j];
        #pragma unroll
        for (int c = 0; c < CC; c++) s += pooled[c] * fc1_w[j*CC + c];
        h[j] = s > 0.f ? s : 0.f;
    }
    float lg[4];
    #pragma unroll
    for (int k = 0; k < 4; k++) {
        float s = fc2_b[k];
        #pragma unroll
        for (int j = 0; j < RR; j++) s += h[j] * fc2_w[k*RR + j];
        lg[k] = s;
    }
    int ep = *epoch_p;
    float tao = (ep >= 60) ? 1.0f : (-(29.0f/60.0f)*(float)ep + 30.0f);
    float inv = 1.0f / tao;
    float m = fmaxf(fmaxf(lg[0], lg[1]), fmaxf(lg[2], lg[3]));
    float e[4], sum = 0.f;
    #pragma unroll
    for (int k = 0; k < 4; k++) { e[k] = __expf((lg[k]-m)*inv); sum += e[k]; }
    float r = 1.0f / sum;
    #pragma unroll
    for (int k = 0; k < 4; k++) g_gate[n*4 + k] = e[k]*r;
}

// ---------------- kernel 3: prep (W^T split -> swizzled images + bias) -------
__global__ void prep_kernel(const float* __restrict__ W, const float* __restrict__ b) {
    int n = blockIdx.x, tid = threadIdx.x;
    float g0 = g_gate[n*4+0], g1 = g_gate[n*4+1], g2 = g_gate[n*4+2], g3 = g_gate[n*4+3];
    for (int p_ = tid; p_ < 2048; p_ += 256) {
        int d = p_ >> 5, c2 = p_ & 31;
        int c0 = 2*c2, c1 = c0 + 1;
        int cd0 = c0*DD + d, cd1 = c1*DD + d;
        float w0 = g0*W[cd0] + g1*W[CC*DD+cd0] + g2*W[2*CC*DD+cd0] + g3*W[3*CC*DD+cd0];
        float w1 = g0*W[cd1] + g1*W[CC*DD+cd1] + g2*W[2*CC*DD+cd1] + g3*W[3*CC*DD+cd1];
        __nv_bfloat16 h0 = __float2bfloat16(w0);
        __nv_bfloat16 h1 = __float2bfloat16(w1);
        __nv_bfloat16 L0 = __float2bfloat16(w0 - __bfloat162float(h0));
        __nv_bfloat16 L1 = __float2bfloat16(w1 - __bfloat162float(h1));
        int slot = (((c2 >> 2) ^ (d & 7)) << 2) + (c2 & 3);
        g_Wspu[((size_t)n*2)*2048 + d*32 + slot]   = packbf(h0, h1);
        g_Wspu[((size_t)n*2+1)*2048 + d*32 + slot] = packbf(L0, L1);
    }
    if (tid < DD)
        g_bf[n*DD + tid] = g0*b[tid] + g1*b[DD+tid] + g2*b[2*DD+tid] + g3*b[3*DD+tid];
}

// ---------------- kernel 4: bf16 mma.sync GEMM (no gather) -------------------
// 1024 blocks = (n, q8 of 32 frames); 4 tiles of 8 frames; warp = frame.
__global__ void __launch_bounds__(256, 1) gemm_kernel() {
    extern __shared__ __align__(16) char sm[];
    float* buf = (float*)(sm + O_BUF);
    short* iv2 = (short*)(sm + O_IV);
    float* bfs = (float*)(sm + O_BFS);
    uint32_t sb = smem_u32(sm);

    int bid = blockIdx.x;
    int n = bid >> 3, q8 = bid & 7;
    int tid = threadIdx.x;
    int w = tid >> 5, l = tid & 31;

    // zero pad rows 25-31 of all 32 At regions (both buffers), stage iv2/bfs
    for (int i = tid; i < 7168; i += 256) {
        int region = i / 224, r = i - region*224;
        ((uint32_t*)sm)[region*1024 + 800 + r] = 0;   // region stride 4096B = 1024 u32
    }
    for (int j = tid; j < 2048; j += 256) iv2[j] = g_iv2[j];
    if (tid < DD) bfs[tid] = g_bf[n*DD + tid];

    // stage W images (group), then tile 0 (group)
    {
        const uint32_t* wg = g_Wspu + (size_t)n*2*2048;
        for (int i = tid; i < 1024; i += 256) {
            int h = i >> 9, j = i & 511;
            cp_async16(sb + (h ? O_WTL : O_WTH) + j*16, wg + h*2048 + j*4);
        }
        CP_COMMIT();
    }
    size_t rowbase = ((size_t)n*TT + q8*32) * 800;
    {
        #pragma unroll
        for (int k = 0; k < 13; k++) {
            int i = tid + k*256;
            if (i < 3200) {
                int fr = i / 400, rem = i - fr*400;
                int h = rem / 200, j = rem - h*200;
                const uint32_t* src = (h ? g_Al : g_Ah) + rowbase + (size_t)fr*800 + j*4;
                cp_async16(sb + O_AT0 + fr*8192 + h*4096 + j*16, src);
            }
        }
        CP_COMMIT();
    }

    uint32_t WhU = sb + O_WTH;
    uint32_t WlU = sb + O_WTL;

    int g = l >> 2, t2 = (l & 3)*2;
    int rA = l & 15, hA = l >> 4;
    int rB = l & 7, kb = (l >> 3) & 1, nh = (l >> 4) & 1;

    float rsum[7], rsq[7];
    #pragma unroll
    for (int k = 0; k < 7; k++) { rsum[k] = 0.f; rsq[k] = 0.f; }

    for (int it = 0; it < NTILES; it++) {
        int t0 = q8*32 + it*TTILE;
        uint32_t curbase = (it & 1) ? O_AT1 : O_AT0;
        uint32_t nxtbase = (it & 1) ? O_AT0 : O_AT1;

        // issue next tile's images (independent buffer)
        if (it + 1 < NTILES) {
            size_t rb2 = rowbase + (size_t)(it + 1)*TTILE*800;
            #pragma unroll
            for (int k = 0; k < 13; k++) {
                int i = tid + k*256;
                if (i < 3200) {
                    int fr = i / 400, rem = i - fr*400;
                    int h = rem / 200, j = rem - h*200;
                    const uint32_t* src = (h ? g_Al : g_Ah) + rb2 + (size_t)fr*800 + j*4;
                    cp_async16(sb + nxtbase + fr*8192 + h*4096 + j*16, src);
                }
            }
            CP_COMMIT();
            CP_WAIT1();                         // cur tile (and W) complete
        } else {
            CP_WAIT0();
        }
        __syncthreads();                        // cur visible; strips reusable

        uint32_t AhU = sb + curbase + w*8192;
        uint32_t AlU = AhU + 4096;

        // ---- mma chain: acc(bias) += Ah*Wh + Ah*Wl + Al*Wh ----
        float acc[64];
        #pragma unroll
        for (int mi = 0; mi < 2; mi++)
            #pragma unroll
            for (int nb = 0; nb < 8; nb++) {
                float b0 = bfs[nb*8 + t2], b1 = bfs[nb*8 + t2 + 1];
                float* a = acc + (mi*8 + nb)*4;
                a[0] = b0; a[1] = b1; a[2] = b0; a[3] = b1;
            }
        #pragma unroll
        for (int kk = 0; kk < 4; kk++) {
            uint32_t ua = (uint32_t)((kk*2 + hA) ^ (rA & 7)) * 16;
            uint32_t aoff = (uint32_t)(rA*128) + ua;
            uint32_t ah0[4], ah1[4], al0[4], al1[4];
            ldm4(AhU + aoff, ah0);
            ldm4(AhU + 16*128 + aoff, ah1);
            ldm4(AlU + aoff, al0);
            ldm4(AlU + 16*128 + aoff, al1);
            uint32_t ub = (uint32_t)((kk*2 + kb) ^ rB) * 16;
            #pragma unroll
            for (int p = 0; p < 4; p++) {
                uint32_t boff = (uint32_t)((p*16 + rB + nh*8)*128) + ub;
                uint32_t bh[4], bl[4];
                ldm4(WhU + boff, bh);
                ldm4(WlU + boff, bl);
                #pragma unroll
                for (int mi = 0; mi < 2; mi++) {
                    const uint32_t* am = mi ? ah1 : ah0;
                    const uint32_t* av = mi ? al1 : al0;
                    float* c0 = acc + (mi*8 + 2*p)*4;
                    float* c1 = acc + (mi*8 + 2*p + 1)*4;
                    mma16816(c0, am, bh);  mma16816(c1, am, bh + 2);
                    mma16816(c0, am, bl);  mma16816(c1, am, bl + 2);
                    mma16816(c0, av, bh);  mma16816(c1, av, bh + 2);
                }
            }
        }

        // ---- scatter accs through iv2 into own strip ----
        {
            float* strip = buf + w*BUFW;
            #pragma unroll
            for (int mi = 0; mi < 2; mi++) {
                int v0r = mi*16 + g;
                int v1r = v0r + 8;
                #pragma unroll
                for (int nb = 0; nb < 8; nb++) {
                    const float* a = acc + (mi*8 + nb)*4;
                    int d = nb*8 + t2;
                    strip[iv2[d*32 + v0r]]     = a[0];
                    strip[iv2[(d+1)*32 + v0r]] = a[1];
                    if (v1r < VV) {
                        strip[iv2[d*32 + v1r]]     = a[2];
                        strip[iv2[(d+1)*32 + v1r]] = a[3];
                    }
                }
            }
        }
        __syncthreads();                        // strips staged

        // ---- stats ----
        #pragma unroll
        for (int k = 0; k < 7; k++) {
            int f = tid + k*256;
            if (f < FEAT) {
                int pa = f + (f >> 6);
                float s = 0.f, q = 0.f;
                #pragma unroll
                for (int w8 = 0; w8 < 8; w8++) {
                    float v = buf[w8*BUFW + pa];
                    s += v; q += v*v;
                }
                rsum[k] += s; rsq[k] += q;
            }
        }
        // ---- coalesced transposed z store [n][d][t0..t0+7][v] ----
        {
            float* zb = g_z + (size_t)n * (CC*TT*VV) + (size_t)t0 * VV;
            #pragma unroll
            for (int k = 0; k < 13; k++) {
                int qd = tid + k*256;
                if (qd < 3200) {
                    int e = qd*4;
                    int d = e / 200;
                    int r = e - d*200;
                    float4 o;
                    #pragma unroll
                    for (int j = 0; j < 4; j++) {
                        int rr = r + j;
                        int tl = rr / 25, v = rr - tl*25;
                        ((float*)&o)[j] = buf[tl*BUFW + v*65 + d];
                    }
                    *(float4*)(zb + (size_t)d*(TT*VV) + r) = o;
                }
            }
        }
        // loop-top sync protects strips before next scatter
    }
    __syncthreads();
    #pragma unroll
    for (int k = 0; k < 7; k++) {
        int f = tid + k*256;
        if (f < FEAT) {
            atomicAdd(&g_sum[f], rsum[k]);
            atomicAdd(&g_sumsq[f], rsq[k]);
        }
    }
}

// ---------------- kernel 5: BN params (inline) + residual + relu -------------
__global__ void __launch_bounds__(256) final_kernel(const float* __restrict__ x0,
                                                    const float* __restrict__ gamma,
                                                    const float* __restrict__ beta,
                                                    float* __restrict__ out) {
    __shared__ float sc[VV], bi[VV];
    int b = blockIdx.x;
    int n = b >> 6, d = b & 63;
    int tid = threadIdx.x;
    if (tid < VV) {
        int f = tid*DD + d;
        const float invn = 1.0f / (float)ROWS;
        float mu = g_sum[f] * invn;
        float var = g_sumsq[f] * invn - mu*mu;
        float s = gamma[f] * rsqrtf(var + 1e-5f);
        sc[tid] = s;
        bi[tid] = beta[f] - mu*s;
    }
    __syncthreads();
    size_t base = (size_t)n * (CC*TT*VV) + (size_t)d * (TT*VV);
    const float4* zp = (const float4*)(g_z + base);
    const float4* xp = (const float4*)(x0 + base);
    float4* op = (float4*)(out + base);
    #pragma unroll
    for (int k = 0; k < 7; k++) {
        int q = tid + k*256;
        if (q < (TT*VV)/4) {
            int e = q*4;
            int v0 = e - (e/25)*25;
            float4 z = zp[q], x = xp[q], o;
            #pragma unroll
            for (int j = 0; j < 4; j++) {
                int v = v0 + j; if (v >= VV) v -= VV;
                float val = ((const float*)&z)[j]*sc[v] + bi[v] + ((const float*)&x)[j];
                ((float*)&o)[j] = val > 0.f ? val : 0.f;
            }
            op[q] = o;
        }
    }
}

// ---------------- launcher ---------------------------------------------------
extern "C" void kernel_launch(void* const* d_in, const int* in_sizes, int n_in,
                              void* d_out, int out_size) {
    const float* x0       = (const float*)d_in[0];
    const int*   epoch    = (const int*)  d_in[1];
    const float* fc1_w    = (const float*)d_in[2];
    const float* fc1_b    = (const float*)d_in[3];
    const float* fc2_w    = (const float*)d_in[4];
    const float* fc2_b    = (const float*)d_in[5];
    const float* W        = (const float*)d_in[6];
    const float* b        = (const float*)d_in[7];
    const float* mask     = (const float*)d_in[8];
    const float* gamma    = (const float*)d_in[9];
    const float* beta     = (const float*)d_in[10];
    const int*   shift_in = (const int*)  d_in[11];
    const int*   shift_out= (const int*)  d_in[12];
    float* out = (float*)d_out;

    cudaFuncSetAttribute(preshift_kernel, cudaFuncAttributeMaxDynamicSharedMemorySize, PS_SMEM);
    cudaFuncSetAttribute(gemm_kernel, cudaFuncAttributeMaxDynamicSharedMemorySize, SM_BYTES);

    table_kernel<<<32, 256>>>(mask, shift_in, shift_out);
    preshift_kernel<<<NN*32, 256, PS_SMEM>>>(x0);
    gate_kernel<<<1, 128>>>(fc1_w, fc1_b, fc2_w, fc2_b, epoch);
    prep_kernel<<<NN, 256>>>(W, b);
    gemm_kernel<<<NN*8, 256, SM_BYTES>>>();
    final_kernel<<<NN*CC, 256>>>(x0, gamma, beta, out);
}